// round 2
// baseline (speedup 1.0000x reference)
#include <cuda_runtime.h>

#define NBv   8
#define ND    512
#define NCHv  3
#define NMIXv 4
#define HD    128
#define NHALF 256          // c-points per block half

typedef unsigned long long u64;

// ---------------- device scratch ----------------
__device__ ulonglong2 g_feat[2][NBv * NCHv * ND];   // partial features per c-half

// ---------------- f32x2 helpers (sm_100a packed math) ----------------
__device__ __forceinline__ u64 fma2(u64 a, u64 b, u64 c) {
    u64 d; asm("fma.rn.f32x2 %0,%1,%2,%3;" : "=l"(d) : "l"(a), "l"(b), "l"(c)); return d;
}
__device__ __forceinline__ u64 add2(u64 a, u64 b) {
    u64 d; asm("add.rn.f32x2 %0,%1,%2;" : "=l"(d) : "l"(a), "l"(b)); return d;
}
__device__ __forceinline__ u64 mul2(u64 a, u64 b) {
    u64 d; asm("mul.rn.f32x2 %0,%1,%2;" : "=l"(d) : "l"(a), "l"(b)); return d;
}
__device__ __forceinline__ u64 pack2(float lo, float hi) {
    u64 d; asm("mov.b64 %0,{%1,%2};" : "=l"(d) : "f"(lo), "f"(hi)); return d;
}
__device__ __forceinline__ void unpack2(float& lo, float& hi, u64 v) {
    asm("mov.b64 {%0,%1},%2;" : "=f"(lo), "=f"(hi) : "l"(v));
}
__device__ __forceinline__ float ex2f(float x) {
    float r; asm("ex2.approx.f32 %0, %1;" : "=f"(r) : "f"(x)); return r;
}
// 128-bit shared load into two packed f32x2 regs
__device__ __forceinline__ void lds2(u64& lo, u64& hi, const float4* p) {
    unsigned a = (unsigned)__cvta_generic_to_shared(p);
    asm volatile("ld.shared.v2.b64 {%0,%1}, [%2];" : "=l"(lo), "=l"(hi) : "r"(a));
}
__device__ __forceinline__ u64 lds1(const float2* p) {
    unsigned a = (unsigned)__cvta_generic_to_shared(p);
    u64 v; asm volatile("ld.shared.b64 %0, [%1];" : "=l"(v) : "r"(a));
    return v;
}

// ---------------- kernel 1: pairwise SM-kernel, c-split across 2 blocks ----
// grid (32, 3, 8): blockIdx.x = tile*2 + half.  256 threads.
// exp arg identity:  -(|ua-uc|^2) = Pa + Pc + 2*u0a*u0c + 2*u1a*u1c,
//   u = x * istd * ALPHA,  P = -(u0^2+u1^2),  ALPHA^2 = 0.5*(2pi)^2*log2(e)
__global__ void __launch_bounds__(256, 3) k_pair(
    const float* __restrict__ xc, const float* __restrict__ yc,
    const float* __restrict__ mu, const float* __restrict__ istd)
{
    __shared__ float4 su0[NHALF], su1[NHALF], sco[NHALF], ssi[NHALF], sP[NHALF];
    __shared__ float2 syy[NHALF];
    __shared__ u64 red[8][32][2];

    const int tile = blockIdx.x >> 1, half = blockIdx.x & 1;
    const int k = blockIdx.y, b = blockIdx.z;
    const int tid = threadIdx.x;

    const float PI2   = 6.2831853071795864f;
    const float ALPHA = 5.3364454f;   // 2pi * sqrt(0.5*log2(e))

    // ---- build c-table for this half (one point per thread) ----
    {
        const int cl = tid;                       // 0..255
        const int c  = half * NHALF + cl;
        const float x0 = xc[((b * ND + c) * 2 + 0) * NCHv + k];
        const float x1 = xc[((b * ND + c) * 2 + 1) * NCHv + k];
        const float y  = yc[(b * ND + c) * NCHv + k];
        float U0[4], U1[4], CO[4], SI[4], P[4];
        #pragma unroll
        for (int m = 0; m < NMIXv; m++) {
            const float u0 = x0 * istd[2 * m + 0] * ALPHA;
            const float u1 = x1 * istd[2 * m + 1] * ALPHA;
            float t = fmaf(x0, mu[2 * m + 0], x1 * mu[2 * m + 1]);
            t -= rintf(t);
            float sn, cn; __sincosf(PI2 * t, &sn, &cn);
            U0[m] = u0; U1[m] = u1; CO[m] = cn; SI[m] = sn;
            P[m] = -fmaf(u0, u0, u1 * u1);
        }
        su0[cl] = make_float4(U0[0], U0[1], U0[2], U0[3]);
        su1[cl] = make_float4(U1[0], U1[1], U1[2], U1[3]);
        sco[cl] = make_float4(CO[0], CO[1], CO[2], CO[3]);
        ssi[cl] = make_float4(SI[0], SI[1], SI[2], SI[3]);
        sP [cl] = make_float4(P[0],  P[1],  P[2],  P[3]);
        syy[cl] = make_float2(y, y);
    }

    // ---- per-lane A-side values (a may be outside this c-half) ----
    const int al = tid & 31;
    const int cs = tid >> 5;
    const int a  = tile * 32 + al;

    u64 a0x2[2], a1x2[2], ca[2], sa[2], Pa[2];
    {
        const float x0 = xc[((b * ND + a) * 2 + 0) * NCHv + k];
        const float x1 = xc[((b * ND + a) * 2 + 1) * NCHv + k];
        float U0[4], U1[4], CO[4], SI[4], P[4];
        #pragma unroll
        for (int m = 0; m < NMIXv; m++) {
            const float u0 = x0 * istd[2 * m + 0] * ALPHA;
            const float u1 = x1 * istd[2 * m + 1] * ALPHA;
            float t = fmaf(x0, mu[2 * m + 0], x1 * mu[2 * m + 1]);
            t -= rintf(t);
            float sn, cn; __sincosf(PI2 * t, &sn, &cn);
            U0[m] = 2.0f * u0; U1[m] = 2.0f * u1; CO[m] = cn; SI[m] = sn;
            P[m] = -fmaf(u0, u0, u1 * u1);
        }
        #pragma unroll
        for (int p = 0; p < 2; p++) {
            a0x2[p] = pack2(U0[2*p], U0[2*p+1]);
            a1x2[p] = pack2(U1[2*p], U1[2*p+1]);
            ca[p]   = pack2(CO[2*p], CO[2*p+1]);
            sa[p]   = pack2(SI[2*p], SI[2*p+1]);
            Pa[p]   = pack2(P[2*p],  P[2*p+1]);
        }
    }
    __syncthreads();

    // ---- pair loop: warp = 32 a-lanes, uniform c-split (broadcast LDS) ----
    u64 acc0 = 0, acc1 = 0;   // f32x2 zeros

    #pragma unroll 2
    for (int c = cs; c < NHALF; c += 8) {
        u64 u0lo, u0hi, u1lo, u1hi, colo, cohi, silo, sihi, plo, phi;
        lds2(u0lo, u0hi, &su0[c]);
        lds2(u1lo, u1hi, &su1[c]);
        lds2(colo, cohi, &sco[c]);
        lds2(silo, sihi, &ssi[c]);
        lds2(plo,  phi,  &sP[c]);
        const u64 yv = lds1(&syy[c]);
        // mix pair 0
        {
            u64 s = add2(Pa[0], plo);
            s = fma2(u0lo, a0x2[0], s);
            s = fma2(u1lo, a1x2[0], s);
            u64 cv = mul2(silo, sa[0]);
            cv = fma2(colo, ca[0], cv);
            float s0, s1; unpack2(s0, s1, s);
            const u64 e = pack2(ex2f(s0), ex2f(s1));
            acc0 = fma2(mul2(e, cv), yv, acc0);
        }
        // mix pair 1
        {
            u64 s = add2(Pa[1], phi);
            s = fma2(u0hi, a0x2[1], s);
            s = fma2(u1hi, a1x2[1], s);
            u64 cv = mul2(sihi, sa[1]);
            cv = fma2(cohi, ca[1], cv);
            float s0, s1; unpack2(s0, s1, s);
            const u64 e = pack2(ex2f(s0), ex2f(s1));
            acc1 = fma2(mul2(e, cv), yv, acc1);
        }
    }

    red[cs][al][0] = acc0;
    red[cs][al][1] = acc1;
    __syncthreads();

    if (tid < 32) {
        u64 f0 = red[0][tid][0], f1 = red[0][tid][1];
        #pragma unroll
        for (int j = 1; j < 8; j++) {
            f0 = add2(f0, red[j][tid][0]);
            f1 = add2(f1, red[j][tid][1]);
        }
        g_feat[half][(b * NCHv + k) * ND + tile * 32 + tid] = make_ulonglong2(f0, f1);
    }
}

// ---------------- kernel 2: fused MLP (w1+mean, layers 2..5) -----------------
// grid 8 (batch), 512 threads
__global__ void __launch_bounds__(512) k_mlp(
    const float* __restrict__ yc,
    const float* __restrict__ w1, const float* __restrict__ b1,
    const float* __restrict__ w2, const float* __restrict__ b2,
    const float* __restrict__ w3, const float* __restrict__ b3,
    const float* __restrict__ w4, const float* __restrict__ b4,
    const float* __restrict__ w5, const float* __restrict__ b5,
    float* __restrict__ out)
{
    __shared__ __align__(16) float4 sf[ND];
    __shared__ float sy[ND];
    __shared__ float sred[4][HD];
    __shared__ __align__(16) float h1[NCHv * HD];
    __shared__ __align__(16) float h2[HD];
    __shared__ __align__(16) float h3[HD];
    __shared__ float out5[NCHv * NMIXv][4];

    const int b = blockIdx.x, tid = threadIdx.x;
    const int j = tid & 127, q = tid >> 7;
    const float Z = 1.0e-4f;

    // ---- layer 1 + mean, per channel ----
    for (int k = 0; k < NCHv; k++) {
        const int bk = b * NCHv + k;
        {
            const int a = tid;          // 512 threads == ND
            const float4 f0 = ((const float4*)g_feat[0])[bk * ND + a];
            const float4 f1 = ((const float4*)g_feat[1])[bk * ND + a];
            const float y  = yc[(b * ND + a) * NCHv + k];
            sf[a] = make_float4(f0.x + f1.x + Z * y, f0.y + f1.y + Z * y,
                                f0.z + f1.z + Z * y, f0.w + f1.w + Z * y);
            sy[a] = y;
        }
        __syncthreads();

        const float wr0 = w1[j * 5 + 0], wr1 = w1[j * 5 + 1], wr2 = w1[j * 5 + 2];
        const float wr3 = w1[j * 5 + 3], wr4 = w1[j * 5 + 4], bb = b1[j];
        float accA = 0.f, accB = 0.f;
        #pragma unroll 4
        for (int a = q; a < ND; a += 8) {
            { const float4 f = sf[a]; const float y = sy[a];
              float h = fmaf(wr0, f.x, bb); h = fmaf(wr1, f.y, h);
              h = fmaf(wr2, f.z, h); h = fmaf(wr3, f.w, h); h = fmaf(wr4, y, h);
              accA += fmaxf(h, 0.f); }
            { const float4 f = sf[a + 4]; const float y = sy[a + 4];
              float h = fmaf(wr0, f.x, bb); h = fmaf(wr1, f.y, h);
              h = fmaf(wr2, f.z, h); h = fmaf(wr3, f.w, h); h = fmaf(wr4, y, h);
              accB += fmaxf(h, 0.f); }
        }
        sred[q][j] = accA + accB;
        __syncthreads();
        if (tid < HD)
            h1[k * HD + tid] = (sred[0][tid] + sred[1][tid] + sred[2][tid] + sred[3][tid])
                               * (1.0f / 512.0f);
        __syncthreads();
    }

    // ---- layer 2: 384 -> 128, 4-way input split ----
    {
        float acc0 = 0.f, acc1 = 0.f;
        const float4* wr = (const float4*)(w2 + j * (NCHv * HD) + q * 96);
        const float4* xv = (const float4*)(h1 + q * 96);
        #pragma unroll 12
        for (int i = 0; i < 24; i += 2) {
            { const float4 w = wr[i], x = xv[i];
              acc0 = fmaf(w.x, x.x, acc0); acc0 = fmaf(w.y, x.y, acc0);
              acc0 = fmaf(w.z, x.z, acc0); acc0 = fmaf(w.w, x.w, acc0); }
            { const float4 w = wr[i+1], x = xv[i+1];
              acc1 = fmaf(w.x, x.x, acc1); acc1 = fmaf(w.y, x.y, acc1);
              acc1 = fmaf(w.z, x.z, acc1); acc1 = fmaf(w.w, x.w, acc1); }
        }
        sred[q][j] = acc0 + acc1;
        __syncthreads();
        if (tid < HD)
            h2[tid] = fmaxf(sred[0][tid] + sred[1][tid] + sred[2][tid] + sred[3][tid]
                            + b2[tid], 0.f);
        __syncthreads();
    }

    // ---- layer 3: 128 -> 128 ----
    {
        float acc0 = 0.f, acc1 = 0.f;
        const float4* wr = (const float4*)(w3 + j * HD + q * 32);
        const float4* xv = (const float4*)(h2 + q * 32);
        #pragma unroll
        for (int i = 0; i < 8; i += 2) {
            { const float4 w = wr[i], x = xv[i];
              acc0 = fmaf(w.x, x.x, acc0); acc0 = fmaf(w.y, x.y, acc0);
              acc0 = fmaf(w.z, x.z, acc0); acc0 = fmaf(w.w, x.w, acc0); }
            { const float4 w = wr[i+1], x = xv[i+1];
              acc1 = fmaf(w.x, x.x, acc1); acc1 = fmaf(w.y, x.y, acc1);
              acc1 = fmaf(w.z, x.z, acc1); acc1 = fmaf(w.w, x.w, acc1); }
        }
        sred[q][j] = acc0 + acc1;
        __syncthreads();
        if (tid < HD)
            h3[tid] = fmaxf(sred[0][tid] + sred[1][tid] + sred[2][tid] + sred[3][tid]
                            + b3[tid], 0.f);
        __syncthreads();
    }

    // ---- layer 4: 128 -> 128 (result into h2, reuse) ----
    {
        float acc0 = 0.f, acc1 = 0.f;
        const float4* wr = (const float4*)(w4 + j * HD + q * 32);
        const float4* xv = (const float4*)(h3 + q * 32);
        #pragma unroll
        for (int i = 0; i < 8; i += 2) {
            { const float4 w = wr[i], x = xv[i];
              acc0 = fmaf(w.x, x.x, acc0); acc0 = fmaf(w.y, x.y, acc0);
              acc0 = fmaf(w.z, x.z, acc0); acc0 = fmaf(w.w, x.w, acc0); }
            { const float4 w = wr[i+1], x = xv[i+1];
              acc1 = fmaf(w.x, x.x, acc1); acc1 = fmaf(w.y, x.y, acc1);
              acc1 = fmaf(w.z, x.z, acc1); acc1 = fmaf(w.w, x.w, acc1); }
        }
        sred[q][j] = acc0 + acc1;
        __syncthreads();
        if (tid < HD)
            h2[tid] = fmaxf(sred[0][tid] + sred[1][tid] + sred[2][tid] + sred[3][tid]
                            + b4[tid], 0.f);
        __syncthreads();
    }

    // ---- layer 5: 128 -> 12 ----
    if (tid < NCHv * NMIXv * 4) {
        const int j5 = tid >> 2, p = tid & 3;
        float acc = 0.f;
        const float4* wr = (const float4*)(w5 + j5 * HD + p * 32);
        const float4* xv = (const float4*)(h2 + p * 32);
        #pragma unroll
        for (int i = 0; i < 8; i++) {
            const float4 w = wr[i], x = xv[i];
            acc = fmaf(w.x, x.x, acc); acc = fmaf(w.y, x.y, acc);
            acc = fmaf(w.z, x.z, acc); acc = fmaf(w.w, x.w, acc);
        }
        out5[j5][p] = acc;
    }
    __syncthreads();
    if (tid < NCHv * NMIXv)
        out[b * (NCHv * NMIXv) + tid] =
            out5[tid][0] + out5[tid][1] + out5[tid][2] + out5[tid][3] + b5[tid];
}

// ---------------- launch ----------------
extern "C" void kernel_launch(void* const* d_in, const int* in_sizes, int n_in,
                              void* d_out, int out_size)
{
    const float* xc   = (const float*)d_in[0];
    const float* yc   = (const float*)d_in[1];
    const float* mu   = (const float*)d_in[2];
    const float* istd = (const float*)d_in[3];
    const float* w1   = (const float*)d_in[4];
    const float* b1   = (const float*)d_in[5];
    const float* w2   = (const float*)d_in[6];
    const float* b2   = (const float*)d_in[7];
    const float* w3   = (const float*)d_in[8];
    const float* b3   = (const float*)d_in[9];
    const float* w4   = (const float*)d_in[10];
    const float* b4   = (const float*)d_in[11];
    const float* w5   = (const float*)d_in[12];
    const float* b5   = (const float*)d_in[13];
    float* out = (float*)d_out;

    dim3 g1(2 * (ND / 32), NCHv, NBv);   // 32 x 3 x 8 = 768 blocks
    k_pair<<<g1, 256>>>(xc, yc, mu, istd);
    k_mlp<<<NBv, 512>>>(yc, w1, b1, w2, b2, w3, b3, w4, b4, w5, b5, out);
}

// round 4
// speedup vs baseline: 1.2965x; 1.2965x over previous
#include <cuda_runtime.h>

#define NBv   8
#define ND    512
#define NCHv  3
#define NMIXv 4
#define HD    128
#define NTILE 16          // 512 / 32 a-tiles

typedef unsigned long long u64;

// ---------------- device scratch ----------------
// per-(b,k,tile) partial sums of relu(layer1) over that tile's 32 a's
__device__ float g_part[NBv * NCHv * NTILE * HD];

// ---------------- f32x2 helpers (sm_100a packed math) ----------------
__device__ __forceinline__ u64 fma2(u64 a, u64 b, u64 c) {
    u64 d; asm("fma.rn.f32x2 %0,%1,%2,%3;" : "=l"(d) : "l"(a), "l"(b), "l"(c)); return d;
}
__device__ __forceinline__ u64 add2(u64 a, u64 b) {
    u64 d; asm("add.rn.f32x2 %0,%1,%2;" : "=l"(d) : "l"(a), "l"(b)); return d;
}
__device__ __forceinline__ u64 mul2(u64 a, u64 b) {
    u64 d; asm("mul.rn.f32x2 %0,%1,%2;" : "=l"(d) : "l"(a), "l"(b)); return d;
}
__device__ __forceinline__ u64 pack2(float lo, float hi) {
    u64 d; asm("mov.b64 %0,{%1,%2};" : "=l"(d) : "f"(lo), "f"(hi)); return d;
}
__device__ __forceinline__ void unpack2(float& lo, float& hi, u64 v) {
    asm("mov.b64 {%0,%1},%2;" : "=f"(lo), "=f"(hi) : "l"(v));
}
__device__ __forceinline__ float ex2f(float x) {
    float r; asm("ex2.approx.f32 %0, %1;" : "=f"(r) : "f"(x)); return r;
}
__device__ __forceinline__ void lds2(u64& lo, u64& hi, const float4* p) {
    unsigned a = (unsigned)__cvta_generic_to_shared(p);
    asm volatile("ld.shared.v2.b64 {%0,%1}, [%2];" : "=l"(lo), "=l"(hi) : "r"(a));
}
__device__ __forceinline__ u64 lds1(const void* p) {
    unsigned a = (unsigned)__cvta_generic_to_shared(p);
    u64 v; asm volatile("ld.shared.b64 %0, [%1];" : "=l"(v) : "r"(a));
    return v;
}

// ---------------- kernel 1: pairwise SM-kernel + fused layer 1 ----------------
// grid (16 tiles, 3 ch, 8 batch), 512 threads. Full 512-point c-table in smem.
//   exp arg: -(|ua-uc|^2) = Pa + Pc + (2u0a)*u0c + (2u1a)*u1c
//   u = x*istd*ALPHA, P = -(u0^2+u1^2), ALPHA^2 = 0.5*(2pi)^2*log2(e)
//   cos(2pi(va-vc)) = ca*cc + sa*sc
// Table storage (40KB) is dead after the pair loop; red/sred alias it (union).
struct Tables {
    float4 A[ND], B[ND], C[ND], D[ND], P[ND];     // 40960 B
};
struct Reduce {
    u64   red[16][32][2];                          // 8192 B
    float sred[4][HD];                             // 2048 B
};

__global__ void __launch_bounds__(512, 3) k_pair(
    const float* __restrict__ xc, const float* __restrict__ yc,
    const float* __restrict__ mu, const float* __restrict__ istd,
    const float* __restrict__ w1p, const float* __restrict__ b1p)
{
    __shared__ union { Tables t; Reduce r; } sm;   // 40960 B
    __shared__ float2 syy[ND];                     //  4096 B  (total 45056 < 48K)

    const int tile = blockIdx.x, k = blockIdx.y, b = blockIdx.z;
    const int tid = threadIdx.x;

    const float PI2   = 6.2831853071795864f;
    const float ALPHA = 5.3364454f;   // 2pi*sqrt(0.5*log2(e))

    // ---- build full c-table (one point per thread) ----
    {
        const int c = tid;
        const float x0 = xc[((b * ND + c) * 2 + 0) * NCHv + k];
        const float x1 = xc[((b * ND + c) * 2 + 1) * NCHv + k];
        const float y  = yc[(b * ND + c) * NCHv + k];
        float U0[4], U1[4], CO[4], SI[4], P[4];
        #pragma unroll
        for (int m = 0; m < NMIXv; m++) {
            const float u0 = x0 * istd[2 * m + 0] * ALPHA;
            const float u1 = x1 * istd[2 * m + 1] * ALPHA;
            float t = fmaf(x0, mu[2 * m + 0], x1 * mu[2 * m + 1]);
            t -= rintf(t);
            float sn, cn; __sincosf(PI2 * t, &sn, &cn);
            U0[m] = u0; U1[m] = u1; CO[m] = cn; SI[m] = sn;
            P[m] = -fmaf(u0, u0, u1 * u1);
        }
        sm.t.A[c] = make_float4(U0[0], U0[1], U1[0], U1[1]);
        sm.t.B[c] = make_float4(CO[0], CO[1], SI[0], SI[1]);
        sm.t.C[c] = make_float4(U0[2], U0[3], U1[2], U1[3]);
        sm.t.D[c] = make_float4(CO[2], CO[3], SI[2], SI[3]);
        sm.t.P[c] = make_float4(P[0], P[1], P[2], P[3]);
        syy[c] = make_float2(y, y);
    }

    // ---- per-lane A-side values ----
    const int al = tid & 31;
    const int cs = tid >> 5;          // c-split 0..15, uniform per warp
    const int a  = tile * 32 + al;

    u64 a0[2], a1[2], ca[2], sa[2], pa[2];
    {
        const float x0 = xc[((b * ND + a) * 2 + 0) * NCHv + k];
        const float x1 = xc[((b * ND + a) * 2 + 1) * NCHv + k];
        float U0[4], U1[4], CO[4], SI[4], P[4];
        #pragma unroll
        for (int m = 0; m < NMIXv; m++) {
            const float u0 = x0 * istd[2 * m + 0] * ALPHA;
            const float u1 = x1 * istd[2 * m + 1] * ALPHA;
            float t = fmaf(x0, mu[2 * m + 0], x1 * mu[2 * m + 1]);
            t -= rintf(t);
            float sn, cn; __sincosf(PI2 * t, &sn, &cn);
            U0[m] = 2.0f * u0; U1[m] = 2.0f * u1; CO[m] = cn; SI[m] = sn;
            P[m] = -fmaf(u0, u0, u1 * u1);
        }
        #pragma unroll
        for (int p = 0; p < 2; p++) {
            a0[p] = pack2(U0[2*p], U0[2*p+1]);
            a1[p] = pack2(U1[2*p], U1[2*p+1]);
            ca[p] = pack2(CO[2*p], CO[2*p+1]);
            sa[p] = pack2(SI[2*p], SI[2*p+1]);
            pa[p] = pack2(P[2*p],  P[2*p+1]);
        }
    }
    __syncthreads();

    // ---- pair loop: warp = 32 a-lanes, uniform c-split (broadcast LDS) ----
    u64 acc0 = 0, acc1 = 0;

    #pragma unroll 2
    for (int c = cs; c < ND; c += 16) {
        const u64 yv = lds1(&syy[c]);
        // mix pair 0
        {
            u64 u0x2, u1x2, cox2, six2;
            lds2(u0x2, u1x2, &sm.t.A[c]);
            lds2(cox2, six2, &sm.t.B[c]);
            const u64 pc = lds1(&sm.t.P[c].x);
            u64 s = add2(pa[0], pc);
            s = fma2(u0x2, a0[0], s);
            s = fma2(u1x2, a1[0], s);
            u64 cv = mul2(six2, sa[0]);
            cv = fma2(cox2, ca[0], cv);
            float s0, s1; unpack2(s0, s1, s);
            acc0 = fma2(mul2(pack2(ex2f(s0), ex2f(s1)), cv), yv, acc0);
        }
        // mix pair 1
        {
            u64 u0x2, u1x2, cox2, six2;
            lds2(u0x2, u1x2, &sm.t.C[c]);
            lds2(cox2, six2, &sm.t.D[c]);
            const u64 pc = lds1(&sm.t.P[c].z);
            u64 s = add2(pa[1], pc);
            s = fma2(u0x2, a0[1], s);
            s = fma2(u1x2, a1[1], s);
            u64 cv = mul2(six2, sa[1]);
            cv = fma2(cox2, ca[1], cv);
            float s0, s1; unpack2(s0, s1, s);
            acc1 = fma2(mul2(pack2(ex2f(s0), ex2f(s1)), cv), yv, acc1);
        }
    }

    // tables are dead from here; red/sred alias them — barrier first
    __syncthreads();
    sm.r.red[cs][al][0] = acc0;
    sm.r.red[cs][al][1] = acc1;
    __syncthreads();

    // ---- reduce 16 c-splits, add zitter; final feature -> red[0][lane] ----
    if (tid < 64) {
        const int lane = tid >> 1, p = tid & 1;
        u64 f = sm.r.red[0][lane][p];
        #pragma unroll
        for (int s = 1; s < 16; s++) f = add2(f, sm.r.red[s][lane][p]);
        const float ya = syy[tile * 32 + lane].x;
        const float zy = 1.0e-4f * ya;
        f = add2(f, pack2(zy, zy));
        sm.r.red[0][lane][p] = f;
    }
    __syncthreads();

    // ---- fused layer 1 on this tile's 32 a's ----
    {
        const int j = tid & 127, q = tid >> 7;
        const float wv0 = w1p[j * 5 + 0], wv1 = w1p[j * 5 + 1], wv2 = w1p[j * 5 + 2];
        const float wv3 = w1p[j * 5 + 3], wv4 = w1p[j * 5 + 4], bb = b1p[j];
        float acc = 0.f;
        #pragma unroll
        for (int aa = 0; aa < 8; aa++) {
            const int lane = q * 8 + aa;
            const float4 f = *(const float4*)&sm.r.red[0][lane][0]; // (m0..m3)
            const float y = syy[tile * 32 + lane].x;
            float h = fmaf(wv0, f.x, bb);
            h = fmaf(wv1, f.y, h);
            h = fmaf(wv2, f.z, h);
            h = fmaf(wv3, f.w, h);
            h = fmaf(wv4, y, h);
            acc += fmaxf(h, 0.f);
        }
        sm.r.sred[q][j] = acc;
    }
    __syncthreads();
    if (tid < HD) {
        g_part[((b * NCHv + k) * NTILE + tile) * HD + tid] =
            sm.r.sred[0][tid] + sm.r.sred[1][tid] + sm.r.sred[2][tid] + sm.r.sred[3][tid];
    }
}

// ---------------- kernel 2: tile reduce + layers 2..5 -----------------
// grid 8 (batch), 512 threads
__global__ void __launch_bounds__(512) k_tail(
    const float* __restrict__ w2, const float* __restrict__ b2,
    const float* __restrict__ w3, const float* __restrict__ b3,
    const float* __restrict__ w4, const float* __restrict__ b4,
    const float* __restrict__ w5, const float* __restrict__ b5,
    float* __restrict__ out)
{
    __shared__ float sred[4][HD];
    __shared__ __align__(16) float h1[NCHv * HD];
    __shared__ __align__(16) float h2[HD];
    __shared__ __align__(16) float h3[HD];
    __shared__ float out5[NCHv * NMIXv][4];

    const int b = blockIdx.x, tid = threadIdx.x;
    const int j = tid & 127, q = tid >> 7;

    // ---- reduce 16 tile-partials per (k,j) -> h1 (mean over 512 a) ----
    if (tid < NCHv * HD) {
        const int kk = tid >> 7, jj = tid & 127;
        const float* p = &g_part[((b * NCHv + kk) * NTILE) * HD + jj];
        float acc = 0.f;
        #pragma unroll
        for (int t = 0; t < NTILE; t++) acc += p[t * HD];
        h1[tid] = acc * (1.0f / 512.0f);
    }
    __syncthreads();

    // ---- layer 2: 384 -> 128 ----
    {
        float acc0 = 0.f, acc1 = 0.f;
        const float4* wr = (const float4*)(w2 + j * (NCHv * HD) + q * 96);
        const float4* xv = (const float4*)(h1 + q * 96);
        #pragma unroll 12
        for (int i = 0; i < 24; i += 2) {
            { const float4 w = wr[i], x = xv[i];
              acc0 = fmaf(w.x, x.x, acc0); acc0 = fmaf(w.y, x.y, acc0);
              acc0 = fmaf(w.z, x.z, acc0); acc0 = fmaf(w.w, x.w, acc0); }
            { const float4 w = wr[i+1], x = xv[i+1];
              acc1 = fmaf(w.x, x.x, acc1); acc1 = fmaf(w.y, x.y, acc1);
              acc1 = fmaf(w.z, x.z, acc1); acc1 = fmaf(w.w, x.w, acc1); }
        }
        sred[q][j] = acc0 + acc1;
        __syncthreads();
        if (tid < HD)
            h2[tid] = fmaxf(sred[0][tid] + sred[1][tid] + sred[2][tid] + sred[3][tid]
                            + b2[tid], 0.f);
        __syncthreads();
    }

    // ---- layer 3: 128 -> 128 ----
    {
        float acc0 = 0.f, acc1 = 0.f;
        const float4* wr = (const float4*)(w3 + j * HD + q * 32);
        const float4* xv = (const float4*)(h2 + q * 32);
        #pragma unroll
        for (int i = 0; i < 8; i += 2) {
            { const float4 w = wr[i], x = xv[i];
              acc0 = fmaf(w.x, x.x, acc0); acc0 = fmaf(w.y, x.y, acc0);
              acc0 = fmaf(w.z, x.z, acc0); acc0 = fmaf(w.w, x.w, acc0); }
            { const float4 w = wr[i+1], x = xv[i+1];
              acc1 = fmaf(w.x, x.x, acc1); acc1 = fmaf(w.y, x.y, acc1);
              acc1 = fmaf(w.z, x.z, acc1); acc1 = fmaf(w.w, x.w, acc1); }
        }
        sred[q][j] = acc0 + acc1;
        __syncthreads();
        if (tid < HD)
            h3[tid] = fmaxf(sred[0][tid] + sred[1][tid] + sred[2][tid] + sred[3][tid]
                            + b3[tid], 0.f);
        __syncthreads();
    }

    // ---- layer 4: 128 -> 128 (into h2) ----
    {
        float acc0 = 0.f, acc1 = 0.f;
        const float4* wr = (const float4*)(w4 + j * HD + q * 32);
        const float4* xv = (const float4*)(h3 + q * 32);
        #pragma unroll
        for (int i = 0; i < 8; i += 2) {
            { const float4 w = wr[i], x = xv[i];
              acc0 = fmaf(w.x, x.x, acc0); acc0 = fmaf(w.y, x.y, acc0);
              acc0 = fmaf(w.z, x.z, acc0); acc0 = fmaf(w.w, x.w, acc0); }
            { const float4 w = wr[i+1], x = xv[i+1];
              acc1 = fmaf(w.x, x.x, acc1); acc1 = fmaf(w.y, x.y, acc1);
              acc1 = fmaf(w.z, x.z, acc1); acc1 = fmaf(w.w, x.w, acc1); }
        }
        sred[q][j] = acc0 + acc1;
        __syncthreads();
        if (tid < HD)
            h2[tid] = fmaxf(sred[0][tid] + sred[1][tid] + sred[2][tid] + sred[3][tid]
                            + b4[tid], 0.f);
        __syncthreads();
    }

    // ---- layer 5: 128 -> 12 ----
    if (tid < NCHv * NMIXv * 4) {
        const int j5 = tid >> 2, p = tid & 3;
        float acc = 0.f;
        const float4* wr = (const float4*)(w5 + j5 * HD + p * 32);
        const float4* xv = (const float4*)(h2 + p * 32);
        #pragma unroll
        for (int i = 0; i < 8; i++) {
            const float4 w = wr[i], x = xv[i];
            acc = fmaf(w.x, x.x, acc); acc = fmaf(w.y, x.y, acc);
            acc = fmaf(w.z, x.z, acc); acc = fmaf(w.w, x.w, acc);
        }
        out5[j5][p] = acc;
    }
    __syncthreads();
    if (tid < NCHv * NMIXv)
        out[b * (NCHv * NMIXv) + tid] =
            out5[tid][0] + out5[tid][1] + out5[tid][2] + out5[tid][3] + b5[tid];
}

// ---------------- launch ----------------
extern "C" void kernel_launch(void* const* d_in, const int* in_sizes, int n_in,
                              void* d_out, int out_size)
{
    const float* xc   = (const float*)d_in[0];
    const float* yc   = (const float*)d_in[1];
    const float* mu   = (const float*)d_in[2];
    const float* istd = (const float*)d_in[3];
    const float* w1   = (const float*)d_in[4];
    const float* b1   = (const float*)d_in[5];
    const float* w2   = (const float*)d_in[6];
    const float* b2   = (const float*)d_in[7];
    const float* w3   = (const float*)d_in[8];
    const float* b3   = (const float*)d_in[9];
    const float* w4   = (const float*)d_in[10];
    const float* b4   = (const float*)d_in[11];
    const float* w5   = (const float*)d_in[12];
    const float* b5   = (const float*)d_in[13];
    float* out = (float*)d_out;

    dim3 g1(NTILE, NCHv, NBv);   // 16 x 3 x 8 = 384 blocks, 512 threads
    k_pair<<<g1, 512>>>(xc, yc, mu, istd, w1, b1);
    k_tail<<<NBv, 512>>>(w2, b2, w3, b3, w4, b4, w5, b5, out);
}